// round 16
// baseline (speedup 1.0000x reference)
#include <cuda_runtime.h>
#include <cuda_fp16.h>
#include <math.h>
#include <stdint.h>

#define NB 2
#define LQ 2048
#define SK 2048
#define HH 8
#define DD 64
#define NHT (NB*HH)
#define NHLD (NB*HH*LQ*DD)   // 2,097,152
#define NROWS (NHT*LQ)       // 32768
#define NCTA 296             // 2 CTAs/SM x 148 SMs, one wave
#define NUNITS 4096          // 256 groups x 16 tiles

// Scratch: phiK fp16 [n][h][s][d]; K partial sums; row maxima
__device__ __align__(256) __half g_Kh[NHLD];
__device__ __align__(256) float g_kpart[1024*DD];
__device__ __align__(256) unsigned int g_rowmax[NROWS];

// ---------------------------------------------------------------------------
// PTX helpers
// ---------------------------------------------------------------------------
__device__ __forceinline__ uint32_t smem_u32_of(const void* p) {
    uint32_t a;
    asm("{ .reg .u64 t; cvta.to.shared.u64 t, %1; cvt.u32.u64 %0, t; }" : "=r"(a) : "l"(p));
    return a;
}
#define LDM4(r, addr) \
    asm volatile("ldmatrix.sync.aligned.m8n8.x4.shared.b16 {%0,%1,%2,%3}, [%4];" \
        : "=r"((r)[0]), "=r"((r)[1]), "=r"((r)[2]), "=r"((r)[3]) : "r"(addr))
#define MMAF16(c, a0, a1, a2, a3, b0, b1) \
    asm volatile("mma.sync.aligned.m16n8k16.row.col.f32.f16.f16.f32 " \
        "{%0,%1,%2,%3}, {%4,%5,%6,%7}, {%8,%9}, {%0,%1,%2,%3};" \
        : "+f"((c)[0]), "+f"((c)[1]), "+f"((c)[2]), "+f"((c)[3]) \
        : "r"(a0), "r"(a1), "r"(a2), "r"(a3), "r"(b0), "r"(b1))
#define CPA16(s, g) \
    asm volatile("cp.async.cg.shared.global [%0], [%1], 16;" :: "r"(s), "l"(g))
#define CPC()  asm volatile("cp.async.commit_group;" ::: "memory")
#define CPW1() asm volatile("cp.async.wait_group 1;" ::: "memory")
#define CPW0() asm volatile("cp.async.wait_group 0;" ::: "memory")

__device__ __forceinline__ float phi32(float x) {
    return (x > 0.f) ? (x + 1.f) : __expf(x);
}

// fp16x2 feature map: phi = x>0 ? x+1 : exp(x)  (h2exp path)
__device__ __forceinline__ __half2 phi_h2(__half2 hx, __half2 scale2) {
    const __half2 one2  = __float2half2_rn(1.0f);
    const __half2 zero2 = __float2half2_rn(0.0f);
    __half2 ex = h2exp(hx);
    __half2 m  = __hgt2(hx, zero2);
    __half2 r  = __hfma2(m, __hsub2(__hadd2(hx, one2), ex), ex);
    return __hmul2(r, scale2);
}

// SMEM: 3 B slots x 16KB + A 16KB = 64KB
#define A_STAGE 49152
#define SMEM_TOTAL 65536

// ---------------------------------------------------------------------------
// Kernel A: K-only prep. feature map + mask + [n,s,h,d]->[n,h,s,d], fp16.
// Each block covers 32 rows of one (n,h); reduces them into g_kpart[block][64].
// Zeroes g_rowmax.
// ---------------------------------------------------------------------------
__global__ __launch_bounds__(256) void prep_kernel(
    const float* __restrict__ k, const float* __restrict__ km)
{
    const int tid = threadIdx.x;
    int idx = blockIdx.x * 256 + tid;              // 8-element chunk index
    if (idx < NROWS) g_rowmax[idx] = 0u;

    int e = idx << 3;
    int d = e & 63;
    int l = (e >> 6) & 2047;
    int h = (e >> 17) & 7;
    int n = e >> 20;
    size_t src = ((((size_t)n * 2048 + l) * 8 + h) << 6) + d;

    float4 k0 = *(const float4*)(k + src);
    float4 k1 = *(const float4*)(k + src + 4);
    const __half2 km2 = __float2half2_rn(km[n * 2048 + l]);

    float fk[8] = {k0.x, k0.y, k0.z, k0.w, k1.x, k1.y, k1.z, k1.w};

    float pk[8];
    uint4 ok;
    uint32_t* pko = (uint32_t*)&ok;
    #pragma unroll
    for (int j = 0; j < 4; j++) {
        __half2 hk = __floats2half2_rn(fk[2*j], fk[2*j+1]);
        __half2 rk = phi_h2(hk, km2);
        pko[j] = *(uint32_t*)&rk;
        float2 fk2 = __half22float2(rk);
        pk[2*j]   = fk2.x;
        pk[2*j+1] = fk2.y;
    }
    ((uint4*)g_Kh)[idx] = ok;

    // --- block-local K partial sum: 32 rows x 64 d -> 64 floats ---
    __shared__ float stage[32][72];
    const int row = tid >> 3;
    const int dc  = (tid & 7) * 8;
    #pragma unroll
    for (int j = 0; j < 8; j++) stage[row][dc + j] = pk[j];
    __syncthreads();
    if (tid < 64) {
        float s = 0.f;
        #pragma unroll
        for (int r = 0; r < 32; r++) s += stage[r][tid];
        g_kpart[blockIdx.x * 64 + tid] = s;
    }
}

// ---------------------------------------------------------------------------
// Kernel C: persistent balanced fp16 HMMA score GEMM.
// grid = 296 CTAs; CTA w owns tile-units [w*4096/296, (w+1)*4096/296).
// unit u -> group g=u>>4 (g = nh*16 + ltile), tile t=u&15 (128 s-cols).
// A tile converted INLINE from queries (phi fp16), once per segment.
// ---------------------------------------------------------------------------
__global__ void __launch_bounds__(256, 2) attn_mma_kernel(
    const float* __restrict__ queries,
    const float* __restrict__ qmask)
{
    extern __shared__ char sm[];
    const uint32_t smu = smem_u32_of(sm);

    const int tid  = threadIdx.x;
    const int lane = tid & 31;
    const int wid  = tid >> 5;
    const int wx   = wid & 1;
    const int wy   = wid >> 1;

    const int mat    = lane >> 3;
    const int rin    = lane & 7;
    const int a_row  = wy * 32 + (mat & 1) * 8 + rin;
    const int a_kc   = mat >> 1;
    const int b_roff = wx * 64 + (mat >> 1) * 8 + rin;
    const int b_kc   = mat & 1;

    const int u0 = (int)(((long long)blockIdx.x * NUNITS) / NCTA);
    const int u1 = (int)(((long long)(blockIdx.x + 1) * NUNITS) / NCTA);

    int u = u0;
    while (u < u1) {
        const int g   = u >> 4;
        const int tb  = u & 15;
        const int nt  = min(16 - tb, u1 - u);
        const int nh  = g >> 4;
        const int l0  = (g & 15) * 128;
        const int n   = nh >> 3;
        const int h   = nh & 7;

        const char* kh_g = (const char*)(g_Kh + ((size_t)nh * SK + (size_t)tb * 128) * DD);

        __syncthreads();   // previous segment fully done (slots + A reusable)

        // prologue: issue first (up to) 2 tiles into slots 0,1
        {
            #pragma unroll
            for (int kk = 0; kk < 4; kk++) {
                int c = tid + kk * 256;
                int row = c >> 3, dc = c & 7;
                uint32_t sw = row * 128 + ((dc ^ (row & 7)) << 4);
                CPA16(smu + sw, kh_g + c * 16);
            }
            CPC();
            if (nt > 1) {
                #pragma unroll
                for (int kk = 0; kk < 4; kk++) {
                    int c = tid + kk * 256;
                    int row = c >> 3, dc = c & 7;
                    uint32_t sw = row * 128 + ((dc ^ (row & 7)) << 4);
                    CPA16(smu + 16384 + sw, kh_g + 32768 + c * 16);
                }
                CPC();
            }
        }

        // stage A: inline phi(queries)*qmask -> fp16, swizzled (once per segment)
        {
            const float* qrow = queries + ((((size_t)n * 2048 + l0) * 8 + h) << 6);
            const float* qmk  = qmask + n * 2048 + l0;
            #pragma unroll
            for (int c4 = 0; c4 < 4; c4++) {
                int c = tid + c4 * 256;            // output 16B chunk, 0..1023
                int row = c >> 3, dc = c & 7;
                const float4* srcp = (const float4*)(qrow + (size_t)row * 512 + dc * 8);
                float4 v0 = srcp[0], v1 = srcp[1];
                __half2 qm2 = __float2half2_rn(qmk[row]);
                float f[8] = {v0.x, v0.y, v0.z, v0.w, v1.x, v1.y, v1.z, v1.w};
                uint4 o;
                uint32_t* po = (uint32_t*)&o;
                #pragma unroll
                for (int j = 0; j < 4; j++) {
                    __half2 hh = __floats2half2_rn(f[2*j], f[2*j+1]);
                    __half2 r  = phi_h2(hh, qm2);
                    po[j] = *(uint32_t*)&r;
                }
                uint32_t dst = row * 128 + ((dc ^ (row & 7)) << 4);
                *(uint4*)(sm + A_STAGE + dst) = o;
            }
        }
        __syncthreads();   // A visible

        uint32_t ah[4][2][4];
        #pragma unroll
        for (int ks = 0; ks < 4; ks++)
            #pragma unroll
            for (int i = 0; i < 2; i++) {
                int ar = a_row + 16 * i;
                uint32_t ad = smu + A_STAGE + ar * 128 + (((a_kc + ks * 2) ^ (ar & 7)) << 4);
                LDM4(ah[ks][i], ad);
            }

        float mA[2] = {0.f, 0.f};
        float mB[2] = {0.f, 0.f};

        for (int tt = 0; tt < nt; tt++) {
            if (tt + 1 < nt) { CPW1(); }
            else             { CPW0(); }
            __syncthreads();                 // tile tt visible; tt-1 compute done
            if (tt + 2 < nt) {
                uint32_t bu = smu + ((tt + 2) % 3) * 16384;
                const char* gk = kh_g + (size_t)(tt + 2) * 32768;
                #pragma unroll
                for (int kk = 0; kk < 4; kk++) {
                    int c = tid + kk * 256;
                    int row = c >> 3, dc = c & 7;
                    uint32_t sw = row * 128 + ((dc ^ (row & 7)) << 4);
                    CPA16(bu + sw, gk + c * 16);
                }
                CPC();
            }

            const uint32_t Bu = smu + (tt % 3) * 16384;
            float acc[2][8][4];
            #pragma unroll
            for (int i = 0; i < 2; i++)
                #pragma unroll
                for (int j = 0; j < 8; j++)
                    acc[i][j][0] = acc[i][j][1] = acc[i][j][2] = acc[i][j][3] = 0.f;

            #pragma unroll
            for (int ks = 0; ks < 4; ks++) {
                const int kb = ks * 2;
                #pragma unroll
                for (int jp = 0; jp < 4; jp++) {
                    int br = b_roff + jp * 16;
                    uint32_t bd = Bu + br * 128 + (((b_kc + kb) ^ (br & 7)) << 4);
                    uint32_t rb[4];
                    LDM4(rb, bd);
                    #pragma unroll
                    for (int i = 0; i < 2; i++) {
                        MMAF16(acc[i][jp*2],   ah[ks][i][0], ah[ks][i][1], ah[ks][i][2], ah[ks][i][3], rb[0], rb[1]);
                        MMAF16(acc[i][jp*2+1], ah[ks][i][0], ah[ks][i][1], ah[ks][i][2], ah[ks][i][3], rb[2], rb[3]);
                    }
                }
            }

            #pragma unroll
            for (int i = 0; i < 2; i++)
                #pragma unroll
                for (int j = 0; j < 8; j++) {
                    mA[i] = fmaxf(mA[i], fmaxf(acc[i][j][0], acc[i][j][1]));
                    mB[i] = fmaxf(mB[i], fmaxf(acc[i][j][2], acc[i][j][3]));
                }
        }

        // segment epilogue: reduce across lane%4, atomicMax (uint==float order, >=0)
        #pragma unroll
        for (int off = 1; off <= 2; off <<= 1) {
            #pragma unroll
            for (int i = 0; i < 2; i++) {
                mA[i] = fmaxf(mA[i], __shfl_xor_sync(0xffffffff, mA[i], off));
                mB[i] = fmaxf(mB[i], __shfl_xor_sync(0xffffffff, mB[i], off));
            }
        }
        if ((lane & 3) == 0) {
            int r = lane >> 2;
            unsigned int* rmp = g_rowmax + nh * LQ + l0;
            #pragma unroll
            for (int i = 0; i < 2; i++) {
                atomicMax(rmp + wy * 32 + i * 16 + r,     __float_as_uint(mA[i]));
                atomicMax(rmp + wy * 32 + i * 16 + r + 8, __float_as_uint(mB[i]));
            }
        }

        u += nt;
    }
}

// ---------------------------------------------------------------------------
// Kernel D: finalize — ksum reduce + mean (phi recomputed fp32) + gate + out.
// 512 blocks; each block = 64 rows of one nh, 4 threads per row.
// ---------------------------------------------------------------------------
__global__ __launch_bounds__(256) void finalize_kernel(
    const float* __restrict__ queries,
    const float* __restrict__ qmask,
    const float* __restrict__ W,
    const float* __restrict__ bias,
    float* __restrict__ out)
{
    const int tid  = threadIdx.x;
    const int r0   = blockIdx.x * 64;
    const int nh   = r0 >> 11;
    const int n    = nh >> 3;
    const int h    = nh & 7;

    __shared__ float ks_s[64];
    if (tid < 64) {
        const float* kp = g_kpart + (nh << 12) + tid;
        float s = 0.f;
        #pragma unroll 16
        for (int b = 0; b < 64; b++) s += kp[b * 64];
        ks_s[tid] = s;
    }
    __syncthreads();

    const int rrow = tid >> 2;
    const int sub  = tid & 3;
    const int grow = r0 + rrow;
    const int l    = grow & 2047;

    size_t obase = ((((size_t)n * LQ + l) * HH + h) << 6) + sub * 16;
    const float4* qs = (const float4*)(queries + obase);
    float4 v[4];
    v[0] = qs[0]; v[1] = qs[1]; v[2] = qs[2]; v[3] = qs[3];

    float dot = 0.f;
    #pragma unroll
    for (int j = 0; j < 4; j++) {
        const float* f = (const float*)&v[j];
        const int db = sub * 16 + j * 4;
        dot += phi32(f[0]) * ks_s[db];
        dot += phi32(f[1]) * ks_s[db + 1];
        dot += phi32(f[2]) * ks_s[db + 2];
        dot += phi32(f[3]) * ks_s[db + 3];
    }
    dot += __shfl_xor_sync(0xffffffff, dot, 1);
    dot += __shfl_xor_sync(0xffffffff, dot, 2);

    const float qmv = qmask[n * LQ + l];
    float mean = dot * qmv * (1.0f / (float)SK);
    float mx = __uint_as_float(g_rowmax[grow]);
    float lg = fmaf(mean, W[0], fmaf(mx, W[1], bias[0]));
    float gate = 1.0f / (1.0f + __expf(-lg));
    float s = gate * qmv;

    float4* dst = (float4*)(out + obase);
    #pragma unroll
    for (int j = 0; j < 4; j++) {
        float4 w = v[j];
        w.x *= s; w.y *= s; w.z *= s; w.w *= s;
        dst[j] = w;
    }
}

// ---------------------------------------------------------------------------
extern "C" void kernel_launch(void* const* d_in, const int* in_sizes, int n_in,
                              void* d_out, int out_size)
{
    const float* queries = (const float*)d_in[0];
    const float* keys    = (const float*)d_in[1];
    const float* q_mask  = (const float*)d_in[3];
    const float* kv_mask = (const float*)d_in[4];
    const float* W       = (const float*)d_in[5];
    const float* b       = (const float*)d_in[6];
    float* out = (float*)d_out;

    prep_kernel<<<(NHLD / 8) / 256, 256>>>(keys, kv_mask);

    cudaFuncSetAttribute(attn_mma_kernel,
                         cudaFuncAttributeMaxDynamicSharedMemorySize, SMEM_TOTAL);
    attn_mma_kernel<<<NCTA, 256, SMEM_TOTAL>>>(queries, q_mask);

    finalize_kernel<<<NROWS / 64, 256>>>(queries, q_mask, W, b, out);
}